// round 4
// baseline (speedup 1.0000x reference)
#include <cuda_runtime.h>
#include <cuda_bf16.h>
#include <cstdint>

#define NN 4096
#define BB 32

#define C_VTH    1.0f
#define C_ALPHA  0.025f
#define C_BETA   0.00025f
#define C_TNOW   10.0f
#define C_INVTV  0.9801986733067553f   /* exp(-1/50) */
#define C_INVTI  0.36787944117144233f  /* exp(-1)    */

// ---- scratch (__device__ globals; no allocation allowed) ----
__device__ uint32_t g_smask[NN];
__device__ uint32_t g_spany[NN];
__device__ float2   g_epm[NN];       // {exp(max_st/50), exp(-max_st/50)}
__device__ float    g_y1[BB * NN];   // S @ W_new
__device__ float    g_y2[BB * NN];   // S @ W_new^T

// ---------------------------------------------------------------------------
// Kernel 1: per-neuron setup (+ exp precompute) + zero y1/y2
// ---------------------------------------------------------------------------
__global__ void k_setup(const float* __restrict__ mem_pot,
                        const float* __restrict__ mem_pot_p,
                        const float* __restrict__ st) {
    const int bx = blockIdx.x, tid = threadIdx.x;
    if (bx < 32) {
        int n = bx * 128 + tid;
        uint32_t sm = 0u, spm = 0u;
#pragma unroll
        for (int b = 0; b < BB; b++) {
            if ((mem_pot[b * NN + n] - C_VTH) > 0.0f)               sm  |= (1u << b);
            if (((mem_pot_p[b * NN + n] - C_VTH) - C_ALPHA) > 0.0f) spm |= (1u << b);
        }
        g_smask[n] = sm;
        g_spany[n] = (spm != 0u) ? 1u : 0u;
        float s = st[n];
        float mst;
        if (sm == 0u)               mst = s;
        else if (sm == 0xFFFFFFFFu) mst = C_TNOW;
        else                        mst = fmaxf(C_TNOW, s);
        float2 e;
        e.x = __expf(mst * 0.02f);
        e.y = __expf(-mst * 0.02f);
        g_epm[n] = e;
    } else {
        const float4 z4 = make_float4(0.f, 0.f, 0.f, 0.f);
        int z = (bx - 32) * 128 + tid;                       // 4096 threads
        for (int i = z; i < (BB * NN) / 4; i += 4096) {
            ((float4*)g_y1)[i] = z4;
            ((float4*)g_y2)[i] = z4;
        }
    }
}

// ---------------------------------------------------------------------------
// Kernel 2: fused W update + y1 partials + y2 partials (all scalar/f32x2).
// Tile = 128 rows x 256 cols. 256 threads. Grid (16 col-groups, 32 row-strips).
//
// Phase 1: thread owns a column PAIR (shared row mask across the pair) and 64
// rows. Per (row, bit): one predicated add.rn.f32x2 accumulating both columns
// of y1. Also writes fp32 W_new to gmem and a bf16 TRANSPOSED tile to smem.
// Phase 2: thread owns a row PAIR (shared column mask) and 64 cols; same
// predicated f32x2 trick for y2. Flush via red.global.add.v2.f32.
// ---------------------------------------------------------------------------
#define TROWS 128
#define TCOLS 256
#define TSTRIDE 65                      /* uint32 words per tileT column (pad) */
#define SM_TILE  0                      /* 256*65 = 16640 words */
#define SM_SREP  16640
#define SM_SREM  (16640 + 128)
#define SM_SAL   (16640 + 256)
#define SM_RMASK (16640 + 384)
#define SM_SCEP  (16640 + 512)
#define SM_SCEM  (16640 + 768)
#define SM_CMASK (16640 + 1024)
#define SM_WORDS (16640 + 1280)
#define DYN_BYTES (SM_WORDS * 4)

#define PADD2(acc, pk, cond)                                                    \
    asm volatile("{\n\t.reg .pred p;\n\tsetp.ne.u32 p, %2, 0;\n\t"              \
                 "@p add.rn.f32x2 %0, %0, %1;\n\t}"                             \
                 : "+l"(acc) : "l"(pk), "r"(cond))

__global__ void __launch_bounds__(256, 1)
k_main(const float* __restrict__ W, float* __restrict__ Wn) {
    extern __shared__ uint32_t smw[];
    float* smf = (float*)smw;
    const int tid = threadIdx.x;
    const int c0 = blockIdx.x * TCOLS;
    const int r0 = blockIdx.y * TROWS;

    for (int i = tid; i < TROWS; i += 256) {
        const float2 e = g_epm[r0 + i];
        smf[SM_SREP + i] = e.x;
        smf[SM_SREM + i] = e.y;
        smf[SM_SAL + i]  = g_spany[r0 + i] ? C_ALPHA : 0.0f;
        smw[SM_RMASK + i] = g_smask[r0 + i];
    }
    for (int i = tid; i < TCOLS; i += 256) {
        const float2 e = g_epm[c0 + i];
        smf[SM_SCEP + i] = e.x;
        smf[SM_SCEM + i] = e.y;
        smw[SM_CMASK + i] = g_smask[c0 + i];
    }
    __syncthreads();

    // ---------------- phase 1: W update + y1 ----------------
    {
        const int pc = tid & 127;              // column pair id
        const int rbase = (tid >> 7) * 64;     // 2 row-halves
        const int c = 2 * pc;
        const float cep0 = smf[SM_SCEP + c],     cem0 = smf[SM_SCEM + c];
        const float cep1 = smf[SM_SCEP + c + 1], cem1 = smf[SM_SCEM + c + 1];
        uint32_t* tcol0 = smw + SM_TILE + (size_t)c * TSTRIDE;
        uint32_t* tcol1 = tcol0 + TSTRIDE;

        unsigned long long acc[32];
#pragma unroll
        for (int b = 0; b < 32; b++) acc[b] = 0ULL;

        float prev0 = 0.0f, prev1 = 0.0f;
#pragma unroll 2
        for (int i = 0; i < 64; i++) {
            const int row = rbase + i;
            const float rep = smf[SM_SREP + row];
            const float rem = smf[SM_SREM + row];
            const float al  = smf[SM_SAL + row];
            const uint32_t m = smw[SM_RMASK + row];
            const size_t gi = (size_t)(r0 + row) * NN + c0 + c;
            const float2 w2 = *(const float2*)(W + gi);
            // exp(|mr-mc|/50) = max(ep_r*em_c, ep_c*em_r)
            const float e0 = fmaxf(rep * cem0, cep0 * rem);
            const float e1 = fmaxf(rep * cem1, cep1 * rem);
            float wn0 = fminf(fmaxf((w2.x + C_BETA) - al * e0, 0.0f), 1.0f);
            float wn1 = fminf(fmaxf((w2.y + C_BETA) - al * e1, 0.0f), 1.0f);
            wn0 = (w2.x > 0.0f) ? wn0 : w2.x;
            wn1 = (w2.y > 0.0f) ? wn1 : w2.y;
            float2 o; o.x = wn0; o.y = wn1;
            *(float2*)(Wn + gi) = o;
            if (i & 1) {
                uint32_t p0, p1;
                // hi = current (odd row), lo = prev (even row)
                asm("cvt.rn.satfinite.bf16x2.f32 %0, %1, %2;"
                    : "=r"(p0) : "f"(wn0), "f"(prev0));
                asm("cvt.rn.satfinite.bf16x2.f32 %0, %1, %2;"
                    : "=r"(p1) : "f"(wn1), "f"(prev1));
                tcol0[row >> 1] = p0;
                tcol1[row >> 1] = p1;
            } else {
                prev0 = wn0;
                prev1 = wn1;
            }
            unsigned long long pk;
            {
                const uint32_t u0 = __float_as_uint(wn0);
                const uint32_t u1 = __float_as_uint(wn1);
                asm("mov.b64 %0, {%1, %2};" : "=l"(pk) : "r"(u0), "r"(u1));
            }
#pragma unroll
            for (int b = 0; b < 32; b++)
                PADD2(acc[b], pk, m & (1u << b));
        }
#pragma unroll
        for (int b = 0; b < 32; b++) {
            uint32_t x, y;
            asm("mov.b64 {%0, %1}, %2;" : "=r"(x), "=r"(y) : "l"(acc[b]));
            float* p = &g_y1[(size_t)b * NN + c0 + c];
            asm volatile("red.global.add.v2.f32 [%0], {%1, %2};"
                         :: "l"(p), "f"(__uint_as_float(x)), "f"(__uint_as_float(y))
                         : "memory");
        }
    }
    __syncthreads();

    // ---------------- phase 2: y2 from bf16 transposed tile ----------------
    {
        const int rp = tid & 63;               // row pair id
        const int cbase = (tid >> 6) * 64;     // 4 col-quarters
        unsigned long long acc[32];
#pragma unroll
        for (int b = 0; b < 32; b++) acc[b] = 0ULL;

#pragma unroll 1
        for (int j = 0; j < 64; j++) {
            const int cc = cbase + j;
            const uint32_t m = smw[SM_CMASK + cc];
            const uint32_t v = smw[SM_TILE + (size_t)cc * TSTRIDE + rp];
            // bf16 -> f32 is a 16-bit left shift
            const uint32_t lo = v << 16;            // even row
            const uint32_t hi = v & 0xFFFF0000u;    // odd row
            unsigned long long pk;
            asm("mov.b64 %0, {%1, %2};" : "=l"(pk) : "r"(lo), "r"(hi));
#pragma unroll
            for (int b = 0; b < 32; b++)
                PADD2(acc[b], pk, m & (1u << b));
        }
#pragma unroll
        for (int b = 0; b < 32; b++) {
            uint32_t x, y;
            asm("mov.b64 {%0, %1}, %2;" : "=r"(x), "=r"(y) : "l"(acc[b]));
            float* p = &g_y2[(size_t)b * NN + r0 + 2 * rp];
            asm volatile("red.global.add.v2.f32 [%0], {%1, %2};"
                         :: "l"(p), "f"(__uint_as_float(x)), "f"(__uint_as_float(y))
                         : "memory");
        }
    }
}

// ---------------------------------------------------------------------------
// Kernel 3: final elementwise integrate / leak / reset / refractory
// ---------------------------------------------------------------------------
__global__ void k_final(const float* __restrict__ inp,
                        const float* __restrict__ mem_pot,
                        const float* __restrict__ mem_cur,
                        const float* __restrict__ mem_pot_p,
                        const float* __restrict__ mem_cur_p,
                        const int*   __restrict__ refrac,
                        float* __restrict__ oS,  float* __restrict__ oMP,
                        float* __restrict__ oMC, float* __restrict__ oMPP,
                        float* __restrict__ oMCP, float* __restrict__ oRef) {
    int i = blockIdx.x * blockDim.x + threadIdx.x;
    if (i >= BB * NN) return;

    const float mp  = mem_pot[i];
    const float mpp = mem_pot_p[i];
    const bool S  = (mp - C_VTH) > 0.0f;
    const bool Sp = ((mpp - C_VTH) - C_ALPHA) > 0.0f;

    const int rf = refrac[i];
    const int rd = (rf > 0) ? (rf - 1) : rf;
    const bool active = (rd == 0);

    const float mc  = mem_cur[i];
    const float mcp = mem_cur_p[i];

    float mcn  = active ? ((inp[i] + g_y1[i]) + mc) : mc;
    float mcpn = active ? (g_y2[i] + mcp)           : mcp;
    float mpn  = active ? (mcn + mp)                : mp;
    float mppn = active ? (mcpn + mpp)              : mpp;

    mpn  *= C_INVTV;
    mcn  *= C_INVTI;
    mppn *= C_INVTV;
    mcpn *= C_INVTI;

    if (S)  mpn  = 0.0f;
    if (Sp) mppn = 0.0f;
    const int rnew = S ? 2 : rd;

    oS[i]   = S ? 1.0f : 0.0f;
    oMP[i]  = mpn;
    oMC[i]  = mcn;
    oMPP[i] = mppn;
    oMCP[i] = mcpn;
    oRef[i] = (float)rnew;
}

// ---------------------------------------------------------------------------
extern "C" void kernel_launch(void* const* d_in, const int* in_sizes, int n_in,
                              void* d_out, int out_size) {
    const float* inp  = (const float*)d_in[0];
    const float* W    = (const float*)d_in[1];
    const float* mp   = (const float*)d_in[2];
    const float* mc   = (const float*)d_in[3];
    const float* mpp  = (const float*)d_in[4];
    const float* mcp  = (const float*)d_in[5];
    const float* st   = (const float*)d_in[6];
    const int*   refr = (const int*)d_in[7];

    float* out  = (float*)d_out;
    float* oS   = out;
    float* oMP  = out + (size_t)BB * NN;
    float* oW   = out + (size_t)2 * BB * NN;
    float* oMC  = oW   + (size_t)NN * NN;
    float* oMPP = oMC  + (size_t)BB * NN;
    float* oMCP = oMPP + (size_t)BB * NN;
    float* oRef = oMCP + (size_t)BB * NN;

    cudaFuncSetAttribute(k_main, cudaFuncAttributeMaxDynamicSharedMemorySize,
                         DYN_BYTES);

    k_setup<<<64, 128>>>(mp, mpp, st);
    k_main<<<dim3(16, 32), 256, DYN_BYTES>>>(W, oW);
    k_final<<<(BB * NN) / 256, 256>>>(inp, mp, mc, mpp, mcp, refr,
                                      oS, oMP, oMC, oMPP, oMCP, oRef);
}

// round 5
// speedup vs baseline: 1.7522x; 1.7522x over previous
#include <cuda_runtime.h>
#include <cstdint>

#define NN 4096
#define BB 32

#define C_VTH    1.0f
#define C_ALPHA  0.025f
#define C_BETA   0.00025f
#define C_TNOW   10.0f
#define C_INVTV  0.9801986733067553f   /* exp(-1/50) */
#define C_INVTI  0.36787944117144233f  /* exp(-1)    */

// ---- scratch (__device__ globals; no allocation allowed) ----
__device__ uint32_t g_smask[NN];
__device__ uint32_t g_spany[NN];
__device__ float2   g_epm[NN];             // {exp(max_st/50), exp(-max_st/50)}
__device__ uint32_t g_sel[1024 * 32];      // [neuron-group of 4][batch] byte-selectors
__device__ float    g_p1[32 * BB * NN];    // y1 partials per row-strip
__device__ float    g_p2[16 * BB * NN];    // y2 partials per col-strip

#define DP4A(acc, a, b) \
    asm("dp4a.u32.u32 %0, %1, %2, %0;" : "+r"(acc) : "r"(a), "r"(b))
#define PRMT(d, a, b, c) \
    asm("prmt.b32 %0, %1, %2, %3;" : "=r"(d) : "r"(a), "r"(b), "r"(c))

// ---------------------------------------------------------------------------
// Kernel 1: masks, max_st exp pair, and DP4A selector table.
// grid 32 x 512 threads: tid = nl + 128*bq; bq handles 8 batches.
// ---------------------------------------------------------------------------
__global__ void k_setup(const float* __restrict__ mem_pot,
                        const float* __restrict__ mem_pot_p,
                        const float* __restrict__ st) {
    __shared__ uint32_t ssm[4][128], sspm[4][128], smf[128];
    const int tid = threadIdx.x;
    const int nl = tid & 127, bq = tid >> 7;
    const int n = blockIdx.x * 128 + nl;

    uint32_t psm = 0u, pspm = 0u;
#pragma unroll
    for (int j = 0; j < 8; j++) {
        const int b = bq * 8 + j;
        if ((mem_pot[b * NN + n] - C_VTH) > 0.0f)                 psm  |= (1u << b);
        if (((mem_pot_p[b * NN + n] - C_VTH) - C_ALPHA) > 0.0f)   pspm |= (1u << b);
    }
    ssm[bq][nl] = psm;
    sspm[bq][nl] = pspm;
    __syncthreads();

    if (tid < 128) {
        const uint32_t sm  = ssm[0][tid] | ssm[1][tid] | ssm[2][tid] | ssm[3][tid];
        const uint32_t spm = sspm[0][tid] | sspm[1][tid] | sspm[2][tid] | sspm[3][tid];
        g_smask[n] = sm;
        g_spany[n] = (spm != 0u) ? 1u : 0u;
        const float s = st[n];
        float mst;
        if (sm == 0u)               mst = s;
        else if (sm == 0xFFFFFFFFu) mst = C_TNOW;
        else                        mst = fmaxf(C_TNOW, s);
        float2 e;
        e.x = __expf(mst * 0.02f);
        e.y = __expf(-mst * 0.02f);
        g_epm[n] = e;
        smf[tid] = sm;
    }
    __syncthreads();

    // selectors: local groups g=0..31, batches b=0..31
    for (int idx = tid; idx < 1024; idx += 512) {
        const int g = idx >> 5, b = idx & 31;
        const uint32_t m0 = smf[4 * g + 0], m1 = smf[4 * g + 1];
        const uint32_t m2 = smf[4 * g + 2], m3 = smf[4 * g + 3];
        const uint32_t sel = ((m0 >> b) & 1u)
                           | (((m1 >> b) & 1u) << 8)
                           | (((m2 >> b) & 1u) << 16)
                           | (((m3 >> b) & 1u) << 24);
        g_sel[blockIdx.x * 1024 + idx] = sel;
    }
}

// ---------------------------------------------------------------------------
// Kernel 2: fused W update + y1/y2 partials via DP4A.
// Tile 128 rows x 256 cols. grid (16 col-strips, 32 row-strips), 256 threads.
// smem word offsets:
// ---------------------------------------------------------------------------
#define OFF_SWQ  0        /* u32 [128][65] packed u8 weights (row-major, 4 cols/word) */
#define OFF_RSEL 8320     /* u32 [32][32] row-group selectors  */
#define OFF_CSEL 9344     /* u32 [64][32] col-group selectors  */
#define OFF_SREP 11392
#define OFF_SREM 11520
#define OFF_SAL  11648
#define OFF_SCEP 11776
#define OFF_SCEM 12032
#define SM_WORDS 12288
#define DYN_BYTES (SM_WORDS * 4)

__global__ void __launch_bounds__(256, 2)
k_main(const float* __restrict__ W, float* __restrict__ Wn) {
    extern __shared__ uint32_t smw[];
    float* smf = (float*)smw;
    const int tid = threadIdx.x;
    const int c0 = blockIdx.x * 256;
    const int r0 = blockIdx.y * 128;

    if (tid < 128) {
        const float2 e = g_epm[r0 + tid];
        smf[OFF_SREP + tid] = e.x;
        smf[OFF_SREM + tid] = e.y;
        smf[OFF_SAL + tid]  = g_spany[r0 + tid] ? C_ALPHA : 0.0f;
    }
    {
        const float2 e = g_epm[c0 + tid];
        smf[OFF_SCEP + tid] = e.x;
        smf[OFF_SCEM + tid] = e.y;
    }
    for (int i = tid; i < 1024; i += 256)
        smw[OFF_RSEL + i] = g_sel[blockIdx.y * 1024 + i];
    for (int i = tid; i < 2048; i += 256)
        smw[OFF_CSEL + i] = g_sel[blockIdx.x * 2048 + i];
    __syncthreads();

    // ---------------- phase 1: streaming W update + u8 pack ----------------
#pragma unroll 4
    for (int it = 0; it < 32; it++) {
        const int i = it * 256 + tid;
        const int row = i >> 6, cg = i & 63;
        const size_t gi = (size_t)(r0 + row) * NN + c0 + 4 * cg;
        const float4 w4 = *(const float4*)(W + gi);
        const float rep = smf[OFF_SREP + row];
        const float rem = smf[OFF_SREM + row];
        const float al  = smf[OFF_SAL + row];
        const float4 cp = ((const float4*)(smf + OFF_SCEP))[cg];
        const float4 cm = ((const float4*)(smf + OFF_SCEM))[cg];
        // exp(|mr-mc|/50) = max(ep_r*em_c, ep_c*em_r)
        float wn0 = fminf(fmaxf((w4.x + C_BETA) - al * fmaxf(rep * cm.x, cp.x * rem), 0.f), 1.f);
        float wn1 = fminf(fmaxf((w4.y + C_BETA) - al * fmaxf(rep * cm.y, cp.y * rem), 0.f), 1.f);
        float wn2 = fminf(fmaxf((w4.z + C_BETA) - al * fmaxf(rep * cm.z, cp.z * rem), 0.f), 1.f);
        float wn3 = fminf(fmaxf((w4.w + C_BETA) - al * fmaxf(rep * cm.w, cp.w * rem), 0.f), 1.f);
        wn0 = (w4.x > 0.0f) ? wn0 : w4.x;
        wn1 = (w4.y > 0.0f) ? wn1 : w4.y;
        wn2 = (w4.z > 0.0f) ? wn2 : w4.z;
        wn3 = (w4.w > 0.0f) ? wn3 : w4.w;
        float4 o; o.x = wn0; o.y = wn1; o.z = wn2; o.w = wn3;
        *(float4*)(Wn + gi) = o;
        const uint32_t q0 = __float2uint_rn(wn0 * 255.0f);
        const uint32_t q1 = __float2uint_rn(wn1 * 255.0f);
        const uint32_t q2 = __float2uint_rn(wn2 * 255.0f);
        const uint32_t q3 = __float2uint_rn(wn3 * 255.0f);
        smw[OFF_SWQ + row * 65 + cg] = q0 | (q1 << 8) | (q2 << 16) | (q3 << 24);
    }
    __syncthreads();

    const float inv255 = 1.0f / 255.0f;

    if (tid < 128) {
        // ---------- phase 2a (warps 0-3): y2[b, r0+row] over this col strip ----------
        const int row = tid;
        uint32_t acc[32];
#pragma unroll
        for (int b = 0; b < 32; b++) acc[b] = 0u;
        const uint32_t* wrow = smw + OFF_SWQ + row * 65;
#pragma unroll 2
        for (int cg = 0; cg < 64; cg++) {
            const uint32_t wq = wrow[cg];
            uint32_t cs[32];
            const uint4* csp = (const uint4*)(smw + OFF_CSEL + cg * 32);
#pragma unroll
            for (int q = 0; q < 8; q++) ((uint4*)cs)[q] = csp[q];
#pragma unroll
            for (int b = 0; b < 32; b++) DP4A(acc[b], wq, cs[b]);
        }
        float* p = g_p2 + (size_t)blockIdx.x * (BB * NN) + (r0 + row);
#pragma unroll
        for (int b = 0; b < 32; b++) p[(size_t)b * NN] = (float)acc[b] * inv255;
    } else {
        // ---------- phase 2b (warps 4-7): y1[b, c0+col] over this row strip ----------
        const int t = tid - 128;
#pragma unroll 1
        for (int pass = 0; pass < 2; pass++) {
            const int col = t + 128 * pass;
            const int cg = col >> 2;
            const uint32_t ctl = (uint32_t)((col & 3) * 17 + 64);  // k | (k+4)<<4
            uint32_t acc[32];
#pragma unroll
            for (int b = 0; b < 32; b++) acc[b] = 0u;
#pragma unroll 2
            for (int rg = 0; rg < 32; rg++) {
                const uint32_t* bp = smw + OFF_SWQ + (4 * rg) * 65 + cg;
                const uint32_t a0 = bp[0], a1 = bp[65], a2 = bp[130], a3 = bp[195];
                uint32_t t0, t1, v;
                PRMT(t0, a0, a1, ctl);
                PRMT(t1, a2, a3, ctl);
                PRMT(v, t0, t1, 0x5410u);
                uint32_t rs[32];
                const uint4* rsp = (const uint4*)(smw + OFF_RSEL + rg * 32);
#pragma unroll
                for (int q = 0; q < 8; q++) ((uint4*)rs)[q] = rsp[q];
#pragma unroll
                for (int b = 0; b < 32; b++) DP4A(acc[b], v, rs[b]);
            }
            float* p = g_p1 + (size_t)blockIdx.y * (BB * NN) + (c0 + col);
#pragma unroll
            for (int b = 0; b < 32; b++) p[(size_t)b * NN] = (float)acc[b] * inv255;
        }
    }
}

// ---------------------------------------------------------------------------
// Kernel 3: slab reduction + final elementwise update
// ---------------------------------------------------------------------------
__global__ void k_final(const float* __restrict__ inp,
                        const float* __restrict__ mem_pot,
                        const float* __restrict__ mem_cur,
                        const float* __restrict__ mem_pot_p,
                        const float* __restrict__ mem_cur_p,
                        const int*   __restrict__ refrac,
                        float* __restrict__ oS,  float* __restrict__ oMP,
                        float* __restrict__ oMC, float* __restrict__ oMPP,
                        float* __restrict__ oMCP, float* __restrict__ oRef) {
    const int i = blockIdx.x * blockDim.x + threadIdx.x;

    float y1 = 0.0f, y2 = 0.0f;
#pragma unroll
    for (int s = 0; s < 32; s++) y1 += g_p1[(size_t)s * (BB * NN) + i];
#pragma unroll
    for (int s = 0; s < 16; s++) y2 += g_p2[(size_t)s * (BB * NN) + i];

    const float mp  = mem_pot[i];
    const float mpp = mem_pot_p[i];
    const bool S  = (mp - C_VTH) > 0.0f;
    const bool Sp = ((mpp - C_VTH) - C_ALPHA) > 0.0f;

    const int rf = refrac[i];
    const int rd = (rf > 0) ? (rf - 1) : rf;
    const bool active = (rd == 0);

    const float mc  = mem_cur[i];
    const float mcp = mem_cur_p[i];

    float mcn  = active ? ((inp[i] + y1) + mc) : mc;
    float mcpn = active ? (y2 + mcp)           : mcp;
    float mpn  = active ? (mcn + mp)           : mp;
    float mppn = active ? (mcpn + mpp)         : mpp;

    mpn  *= C_INVTV;
    mcn  *= C_INVTI;
    mppn *= C_INVTV;
    mcpn *= C_INVTI;

    if (S)  mpn  = 0.0f;
    if (Sp) mppn = 0.0f;
    const int rnew = S ? 2 : rd;

    oS[i]   = S ? 1.0f : 0.0f;
    oMP[i]  = mpn;
    oMC[i]  = mcn;
    oMPP[i] = mppn;
    oMCP[i] = mcpn;
    oRef[i] = (float)rnew;
}

// ---------------------------------------------------------------------------
extern "C" void kernel_launch(void* const* d_in, const int* in_sizes, int n_in,
                              void* d_out, int out_size) {
    const float* inp  = (const float*)d_in[0];
    const float* W    = (const float*)d_in[1];
    const float* mp   = (const float*)d_in[2];
    const float* mc   = (const float*)d_in[3];
    const float* mpp  = (const float*)d_in[4];
    const float* mcp  = (const float*)d_in[5];
    const float* st   = (const float*)d_in[6];
    const int*   refr = (const int*)d_in[7];

    float* out  = (float*)d_out;
    float* oS   = out;
    float* oMP  = out + (size_t)BB * NN;
    float* oW   = out + (size_t)2 * BB * NN;
    float* oMC  = oW   + (size_t)NN * NN;
    float* oMPP = oMC  + (size_t)BB * NN;
    float* oMCP = oMPP + (size_t)BB * NN;
    float* oRef = oMCP + (size_t)BB * NN;

    cudaFuncSetAttribute(k_main, cudaFuncAttributeMaxDynamicSharedMemorySize,
                         DYN_BYTES);

    k_setup<<<32, 512>>>(mp, mpp, st);
    k_main<<<dim3(16, 32), 256, DYN_BYTES>>>(W, oW);
    k_final<<<(BB * NN) / 256, 256>>>(inp, mp, mc, mpp, mcp, refr,
                                      oS, oMP, oMC, oMPP, oMCP, oRef);
}